// round 15
// baseline (speedup 1.0000x reference)
#include <cuda_runtime.h>
#include <cuda_fp16.h>
#include <cstdint>

#define BN 8192
#define CDIM 256
#define MT 64
#define NT 64
#define NTHREADS 384
#define ROWB 512            // f16 tile row bytes
#define ROWB8 256           // fp8 tile row bytes

#define Q8_OFF 0                      // Q fp8: 64 x 256B = 16KB
#define K_OFF 16384                   // per group: K16 (32KB) + K8 (16KB)
#define GSTRIDE 49152
#define P_OFF 163840                  // P: 3 groups x 8KB
#define SMEM_TOTAL 188416
// epilogue overlays (Q8/K dead by then)
#define OFF_OACC 16384                // 64 x 256 f32 accum (64KB)
#define OFF_DN   81920                // 3 x 64 f32 denoms

__device__ float         g_f32[BN * CDIM];  // normalized f (fp32, blend)
__device__ __half        g_fh[BN * CDIM];   // normalized f (f16: V operand)
__device__ unsigned char g_q8[BN * CDIM];   // normalized f (e4m3: Q/K operand)

// ---------------------------------------------------------------- helpers
__device__ __forceinline__ uint32_t smem_u32(const void* p) {
    uint32_t a;
    asm("{ .reg .u64 t; cvta.to.shared.u64 t, %1; cvt.u32.u64 %0, t; }" : "=r"(a) : "l"(p));
    return a;
}
__device__ __forceinline__ void cp16(uint32_t dst, const void* src) {
    asm volatile("cp.async.cg.shared.global [%0], [%1], 16;" :: "r"(dst), "l"(src));
}
#define CP_COMMIT() asm volatile("cp.async.commit_group;" ::: "memory")

__device__ __forceinline__ void ldsm4(uint32_t a, uint32_t& r0, uint32_t& r1,
                                      uint32_t& r2, uint32_t& r3) {
    asm volatile("ldmatrix.sync.aligned.m8n8.x4.shared.b16 {%0,%1,%2,%3}, [%4];"
                 : "=r"(r0), "=r"(r1), "=r"(r2), "=r"(r3) : "r"(a));
}
__device__ __forceinline__ void ldsm4t(uint32_t a, uint32_t& r0, uint32_t& r1,
                                       uint32_t& r2, uint32_t& r3) {
    asm volatile("ldmatrix.sync.aligned.m8n8.x4.trans.shared.b16 {%0,%1,%2,%3}, [%4];"
                 : "=r"(r0), "=r"(r1), "=r"(r2), "=r"(r3) : "r"(a));
}
// fp8 S GEMM: e4m3 x e4m3 -> f32, k=32
__device__ __forceinline__ void mmaQ(float (&c)[4], uint32_t a0, uint32_t a1,
                                     uint32_t a2, uint32_t a3,
                                     uint32_t b0, uint32_t b1) {
    asm volatile("mma.sync.aligned.m16n8k32.row.col.f32.e4m3.e4m3.f32 "
                 "{%0,%1,%2,%3}, {%4,%5,%6,%7}, {%8,%9}, {%0,%1,%2,%3};"
                 : "+f"(c[0]), "+f"(c[1]), "+f"(c[2]), "+f"(c[3])
                 : "r"(a0), "r"(a1), "r"(a2), "r"(a3), "r"(b0), "r"(b1));
}
// f16 O GEMM (unchanged from R13)
__device__ __forceinline__ void mmaH(uint32_t (&c)[2], uint32_t a0, uint32_t a1,
                                     uint32_t a2, uint32_t a3,
                                     uint32_t b0, uint32_t b1) {
    asm volatile("mma.sync.aligned.m16n8k16.row.col.f16.f16.f16.f16 "
                 "{%0,%1}, {%2,%3,%4,%5}, {%6,%7}, {%0,%1};"
                 : "+r"(c[0]), "+r"(c[1])
                 : "r"(a0), "r"(a1), "r"(a2), "r"(a3), "r"(b0), "r"(b1));
}
__device__ __forceinline__ int oacc_addr(int row, int cb) {  // 64x256 f32, 1024B rows
    return OFF_OACC + row * 1024 + ((((cb >> 4) ^ (row & 7)) << 4) | (cb & 15));
}

// ---------------------------------------------------------------------------
// Kernel 1: row L2-normalize; emits fp32 + f16 + e4m3 copies
// ---------------------------------------------------------------------------
__global__ void __launch_bounds__(256) norm_kernel(const float* __restrict__ in) {
    int row  = blockIdx.x * 8 + (threadIdx.x >> 5);
    int lane = threadIdx.x & 31;
    const float* r = in + (size_t)row * CDIM;
    float v[8]; float ss = 0.f;
#pragma unroll
    for (int i = 0; i < 8; i++) { v[i] = r[lane + 32 * i]; ss = fmaf(v[i], v[i], ss); }
#pragma unroll
    for (int o = 16; o > 0; o >>= 1) ss += __shfl_xor_sync(0xffffffffu, ss, o);
    float inv = 1.0f / fmaxf(sqrtf(ss), 1e-12f);
    float*         o32 = g_f32 + (size_t)row * CDIM;
    __half*        ofh = g_fh  + (size_t)row * CDIM;
    unsigned char* o8  = g_q8  + (size_t)row * CDIM;
#pragma unroll
    for (int i = 0; i < 8; i++) {
        float x = v[i] * inv;
        o32[lane + 32 * i] = x;
        ofh[lane + 32 * i] = __float2half(x);
        unsigned short u;
        asm("cvt.rn.satfinite.e4m3x2.f32 %0, %1, %2;" : "=h"(u) : "f"(x), "f"(x));
        o8[lane + 32 * i] = (unsigned char)u;
    }
}

// Load one 64x256 f16 tile (32KB) with the group's 128 threads.
__device__ __forceinline__ void load_k16(uint32_t dst, int tile, int t128) {
    const __half* src = g_fh + (size_t)tile * NT * CDIM;
#pragma unroll
    for (int q = 0; q < 16; q++) {
        int i = t128 + q * 128, row = i >> 5, u = i & 31;
        cp16(dst + row * ROWB + ((u << 4) ^ ((row & 7) << 4)),
             src + (size_t)row * CDIM + u * 8);
    }
}
// Load one 64x256 fp8 tile (16KB) with the group's 128 threads.
__device__ __forceinline__ void load_k8(uint32_t dst, int tile, int t128) {
    const unsigned char* src = g_q8 + (size_t)tile * NT * CDIM;
#pragma unroll
    for (int q = 0; q < 8; q++) {
        int i = t128 + q * 128, row = i >> 4, u = i & 15;
        cp16(dst + row * ROWB8 + (((u ^ (row & 7))) << 4),
             src + (size_t)row * CDIM + u * 16);
    }
}

// ---------------------------------------------------------------------------
// Kernel 2: 3 decoupled key-groups x 4 warps. S GEMM in e4m3 (k32, f32 acc),
// O GEMM in f16 (n-split via P smem exchange). Scores in [-1,1] -> no max.
// ---------------------------------------------------------------------------
__global__ void __launch_bounds__(NTHREADS, 1) attn_kernel(float* __restrict__ out) {
    extern __shared__ char smem[];
    const uint32_t sb = smem_u32(smem);
    const int tid  = threadIdx.x;
    const int lane = tid & 31;
    const int wid  = tid >> 5;
    const int wm   = wid & 3;
    const int gg   = wid >> 2;
    const int t128 = tid & 127;
    const int g    = lane >> 2;
    const int tg   = lane & 3;
    const int qbase = blockIdx.x * MT;

    const int GBASE = (gg == 0) ? 0 : (gg == 1 ? 43 : 86);
    const int NITER = (gg == 2) ? 42 : 43;
    const uint32_t k16b = sb + K_OFF + (uint32_t)gg * GSTRIDE;
    const uint32_t k8b  = k16b + 32768u;
    const uint32_t pbase = sb + P_OFF + (uint32_t)gg * 8192u;
    char* const pbytes   = smem + P_OFF + gg * 8192;

    // prologue: Q8 (all threads) + K8(T0); then K16(T0)
    for (int i = tid; i < 1024; i += NTHREADS) {
        int row = i >> 4, u = i & 15;
        cp16(sb + Q8_OFF + row * ROWB8 + ((u ^ (row & 7)) << 4),
             g_q8 + (size_t)(qbase + row) * CDIM + u * 16);
    }
    load_k8(k8b, GBASE, t128);
    CP_COMMIT();
    load_k16(k16b, GBASE, t128);
    CP_COMMIT();
    asm volatile("cp.async.wait_group 1;" ::: "memory");
    __syncthreads();     // Q8 + all groups' K8(T0) visible

    // --- address components ---
    // S-phase A (Q fp8): 16 rows x 32B per k-step
    const int rowA = wm * 16 + (lane & 15);
    const uint32_t aBase = sb + Q8_OFF + rowA * ROWB8;
    const int uA = (lane >> 4), swzA = rowA & 7;
    // S-phase B (K fp8): 16 keys x 32B per k-step
    const int rowB0 = (lane & 7) + ((lane >> 4) << 3);
    const int uB = (lane >> 3) & 1, swzB = rowB0 & 7;
    // O-phase B (V f16, trans)
    const int rowV0 = (lane & 7) + (((lane >> 3) & 1) << 3);
    const int chV = (lane >> 4) << 4, swzV = (lane & 7) << 4;
    // O-phase A (P f16 tile)
    const int rowPA = lane & 15;
    const uint32_t pldBase = pbase + rowPA * 128;
    const int chP = (lane >> 4) << 4, swzP = (rowPA & 7) << 4;

    uint32_t O[4][8][2];
#pragma unroll
    for (int mb = 0; mb < 4; mb++)
#pragma unroll
        for (int nb = 0; nb < 8; nb++) { O[mb][nb][0] = 0u; O[mb][nb][1] = 0u; }
    float d0 = 0.f, d1 = 0.f;

#pragma unroll 1
    for (int it = 0; it < NITER; it++) {
        if (it > 0) {
            asm volatile("cp.async.wait_group 1;" ::: "memory");   // K8(it) done
            asm volatile("bar.sync %0, 128;" :: "r"(gg + 1) : "memory");
        }

        // ---- S = Q @ K^T : e4m3, k32, f32 accum (16 rows x 64 keys/warp) ----
        float S[8][4];
#pragma unroll
        for (int nb = 0; nb < 8; nb++) { S[nb][0] = S[nb][1] = S[nb][2] = S[nb][3] = 0.f; }
#pragma unroll
        for (int ks = 0; ks < 8; ks++) {
            uint32_t a0, a1, a2, a3;
            ldsm4(aBase + (uint32_t)(((2 * ks + uA) ^ swzA) << 4), a0, a1, a2, a3);
#pragma unroll
            for (int jb = 0; jb < 4; jb++) {
                uint32_t b0, b1, b2, b3;
                ldsm4(k8b + (rowB0 + 16 * jb) * ROWB8
                          + (uint32_t)(((2 * ks + uB) ^ swzB) << 4), b0, b1, b2, b3);
                mmaQ(S[2 * jb],     a0, a1, a2, a3, b0, b1);
                mmaQ(S[2 * jb + 1], a0, a1, a2, a3, b2, b3);
            }
        }

        // ---- P = exp(S) (f32 in, f16 out); denominators; store P slice ----
        {
            char* prow = pbytes + (wm * 16 + g) * 128 + 4 * tg;
#pragma unroll
            for (int nb = 0; nb < 8; nb++) {
                float e0 = __expf(S[nb][0]), e1 = __expf(S[nb][1]);   // row g
                float e2 = __expf(S[nb][2]), e3 = __expf(S[nb][3]);   // row g+8
                d0 += e0 + e1;  d1 += e2 + e3;
                uint32_t plo, phi;
                asm("cvt.rn.f16x2.f32 %0, %1, %2;" : "=r"(plo) : "f"(e1), "f"(e0));
                asm("cvt.rn.f16x2.f32 %0, %1, %2;" : "=r"(phi) : "f"(e3), "f"(e2));
                const int u = (nb ^ g) << 4;
                *(uint32_t*)(prow + u)        = plo;
                *(uint32_t*)(prow + 1024 + u) = phi;
            }
        }
        asm volatile("cp.async.wait_group 0;" ::: "memory");          // K16(it) done
        asm volatile("bar.sync %0, 128;" :: "r"(gg + 1) : "memory");  // P + K16 visible

        // K8(it) fully consumed by all warps -> prefetch K8(it+1) over it
        if (it + 1 < NITER) { load_k8(k8b, GBASE + it + 1, t128); CP_COMMIT(); }

        // ---- O += P @ V : f16, n-split (warp owns 64 cols x all 64 rows) ----
#pragma unroll
        for (int ks = 0; ks < 4; ks++) {
            uint32_t pa[4][4];
#pragma unroll
            for (int mb = 0; mb < 4; mb++)
                ldsm4(pldBase + mb * 2048 + (uint32_t)((32 * ks + chP) ^ swzP),
                      pa[mb][0], pa[mb][1], pa[mb][2], pa[mb][3]);
            const uint32_t vrow = k16b + (rowV0 + 16 * ks) * ROWB;
#pragma unroll
            for (int nq = 0; nq < 4; nq++) {
                uint32_t b0, b1, b2, b3;
                ldsm4t(vrow + (uint32_t)((128 * wm + 32 * nq + chV) ^ swzV),
                       b0, b1, b2, b3);
#pragma unroll
                for (int mb = 0; mb < 4; mb++) {
                    mmaH(O[mb][2 * nq],     pa[mb][0], pa[mb][1], pa[mb][2], pa[mb][3], b0, b1);
                    mmaH(O[mb][2 * nq + 1], pa[mb][0], pa[mb][1], pa[mb][2], pa[mb][3], b2, b3);
                }
            }
        }

        asm volatile("bar.sync %0, 128;" :: "r"(gg + 1) : "memory");  // K16,P reads done
        if (it + 1 < NITER) { load_k16(k16b, GBASE + it + 1, t128); CP_COMMIT(); }
    }

    // ---- denominators: quad reduce ----
#pragma unroll
    for (int off = 1; off <= 2; off <<= 1) {
        d0 += __shfl_xor_sync(0xffffffffu, d0, off);
        d1 += __shfl_xor_sync(0xffffffffu, d1, off);
    }

    // ---- epilogue: sum group O partials into 64x256 f32 smem tile ----
    __syncthreads();
    float* sDN = (float*)(smem + OFF_DN);
    if (tg == 0) {
        sDN[gg * 64 + wm * 16 + g]     = d0;
        sDN[gg * 64 + wm * 16 + g + 8] = d1;
    }
    if (gg == 0) {
#pragma unroll
        for (int mb = 0; mb < 4; mb++)
#pragma unroll
            for (int nb = 0; nb < 8; nb++) {
                int row = 16 * mb + g;
                int cb  = wm * 256 + nb * 32 + tg * 8;
                *(float2*)(smem + oacc_addr(row, cb))     = __half22float2(*(__half2*)&O[mb][nb][0]);
                *(float2*)(smem + oacc_addr(row + 8, cb)) = __half22float2(*(__half2*)&O[mb][nb][1]);
            }
    }
    __syncthreads();
#pragma unroll 1
    for (int turn = 1; turn <= 2; turn++) {
        if (gg == turn) {
#pragma unroll
            for (int mb = 0; mb < 4; mb++)
#pragma unroll
                for (int nb = 0; nb < 8; nb++) {
                    int row = 16 * mb + g;
                    int cb  = wm * 256 + nb * 32 + tg * 8;
                    float2* a0 = (float2*)(smem + oacc_addr(row, cb));
                    float2* a1 = (float2*)(smem + oacc_addr(row + 8, cb));
                    float2 v0 = __half22float2(*(__half2*)&O[mb][nb][0]);
                    float2 v1 = __half22float2(*(__half2*)&O[mb][nb][1]);
                    float2 c0 = *a0, c1 = *a1;
                    a0->x = c0.x + v0.x; a0->y = c0.y + v0.y;
                    a1->x = c1.x + v1.x; a1->y = c1.y + v1.y;
                }
        }
        __syncthreads();
    }

    // ---- final: blend with f, renormalize rows, write out ----
#pragma unroll 1
    for (int r = wid; r < MT; r += 12) {
        float dsum = sDN[r] + sDN[64 + r] + sDN[128 + r];
        float invd = 0.2f / dsum;
        const float* frow = g_f32 + (size_t)(qbase + r) * CDIM;
        float y[8]; float ss = 0.f;
#pragma unroll
        for (int i = 0; i < 8; i++) {
            int col = lane + 32 * i;
            float o = *(float*)(smem + oacc_addr(r, col * 4));
            y[i] = fmaf(0.8f, frow[col], invd * o);
            ss = fmaf(y[i], y[i], ss);
        }
#pragma unroll
        for (int off = 16; off > 0; off >>= 1) ss += __shfl_xor_sync(0xffffffffu, ss, off);
        float inv = 1.0f / fmaxf(sqrtf(ss), 1e-12f);
        float* orow = out + (size_t)(qbase + r) * CDIM;
#pragma unroll
        for (int i = 0; i < 8; i++) orow[lane + 32 * i] = y[i] * inv;
    }
}

// ---------------------------------------------------------------------------
extern "C" void kernel_launch(void* const* d_in, const int* in_sizes, int n_in,
                              void* d_out, int out_size) {
    const float* feats = (const float*)d_in[0];
    float*       out   = (float*)d_out;
    (void)in_sizes; (void)n_in; (void)out_size;

    cudaFuncSetAttribute(attn_kernel,
                         cudaFuncAttributeMaxDynamicSharedMemorySize, SMEM_TOTAL);

    norm_kernel<<<BN / 8, 256>>>(feats);
    attn_kernel<<<BN / MT, NTHREADS, SMEM_TOTAL>>>(out);
}

// round 16
// speedup vs baseline: 1.2306x; 1.2306x over previous
#include <cuda_runtime.h>
#include <cuda_fp16.h>
#include <cstdint>

#define BN 8192
#define CDIM 256
#define MT 64
#define NT 64
#define NTHREADS 384
#define ROWB 512            // smem bytes per K/Q tile row (256 f16)
#define HALF_B 16384        // one 32-key half-tile

#define SQ_OFF 0                      // Q: 64 x 512B = 32KB
#define SK_OFF 32768                  // K: 3 groups x (3 half-slots x 16KB)
#define GSTRIDE 49152
#define SP_OFF 180224                 // P: 3 groups x 8KB (64 x 128B)
#define SMEM_TOTAL 204800
#define OFF_DN 65536                  // epilogue denom overlay (3 x 64 f32)

// structural phase stagger between key-groups (~1/3 tile per group)
#define STAGGER_CYC 2900ull

__device__ float  g_f32[BN * CDIM];   // normalized f (fp32, blend)
__device__ __half g_fh[BN * CDIM];    // normalized f (f16, MMA operand)

// ---------------------------------------------------------------- helpers
__device__ __forceinline__ uint32_t smem_u32(const void* p) {
    uint32_t a;
    asm("{ .reg .u64 t; cvta.to.shared.u64 t, %1; cvt.u32.u64 %0, t; }" : "=r"(a) : "l"(p));
    return a;
}
__device__ __forceinline__ void cp16(uint32_t dst, const void* src) {
    asm volatile("cp.async.cg.shared.global [%0], [%1], 16;" :: "r"(dst), "l"(src));
}
#define CP_COMMIT() asm volatile("cp.async.commit_group;" ::: "memory")

__device__ __forceinline__ void ldsm4(uint32_t a, uint32_t& r0, uint32_t& r1,
                                      uint32_t& r2, uint32_t& r3) {
    asm volatile("ldmatrix.sync.aligned.m8n8.x4.shared.b16 {%0,%1,%2,%3}, [%4];"
                 : "=r"(r0), "=r"(r1), "=r"(r2), "=r"(r3) : "r"(a));
}
__device__ __forceinline__ void ldsm4t(uint32_t a, uint32_t& r0, uint32_t& r1,
                                       uint32_t& r2, uint32_t& r3) {
    asm volatile("ldmatrix.sync.aligned.m8n8.x4.trans.shared.b16 {%0,%1,%2,%3}, [%4];"
                 : "=r"(r0), "=r"(r1), "=r"(r2), "=r"(r3) : "r"(a));
}
__device__ __forceinline__ void mmaH(uint32_t (&c)[2], uint32_t a0, uint32_t a1,
                                     uint32_t a2, uint32_t a3,
                                     uint32_t b0, uint32_t b1) {
    asm volatile("mma.sync.aligned.m16n8k16.row.col.f16.f16.f16.f16 "
                 "{%0,%1}, {%2,%3,%4,%5}, {%6,%7}, {%0,%1};"
                 : "+r"(c[0]), "+r"(c[1])
                 : "r"(a0), "r"(a1), "r"(a2), "r"(a3), "r"(b0), "r"(b1));
}
__device__ __forceinline__ uint32_t exp_h2(uint32_t s) {   // ex2(s*log2e), f16x2
    uint32_t p;
    asm("{ .reg .b32 t;\n\t"
        "mul.rn.f16x2 t, %1, %2;\n\t"
        "ex2.approx.f16x2 %0, t; }"
        : "=r"(p) : "r"(s), "r"(0x3DC53DC5u));
    return p;
}
__device__ __forceinline__ int oacc_addr(int row, int cb) {  // 64x256 f32, 1024B rows
    return row * 1024 + ((((cb >> 4) ^ (row & 7)) << 4) | (cb & 15));
}

// ---------------------------------------------------------------------------
// Kernel 1: row L2-normalize
// ---------------------------------------------------------------------------
__global__ void __launch_bounds__(256) norm_kernel(const float* __restrict__ in) {
    int row  = blockIdx.x * 8 + (threadIdx.x >> 5);
    int lane = threadIdx.x & 31;
    const float* r = in + (size_t)row * CDIM;
    float v[8]; float ss = 0.f;
#pragma unroll
    for (int i = 0; i < 8; i++) { v[i] = r[lane + 32 * i]; ss = fmaf(v[i], v[i], ss); }
#pragma unroll
    for (int o = 16; o > 0; o >>= 1) ss += __shfl_xor_sync(0xffffffffu, ss, o);
    float inv = 1.0f / fmaxf(sqrtf(ss), 1e-12f);
    float*  o32 = g_f32 + (size_t)row * CDIM;
    __half* ofh = g_fh  + (size_t)row * CDIM;
#pragma unroll
    for (int i = 0; i < 8; i++) {
        float x = v[i] * inv;
        o32[lane + 32 * i] = x;
        ofh[lane + 32 * i] = __float2half(x);
    }
}

// Load one 32-key half-tile (16KB) with the group's 128 threads.
__device__ __forceinline__ void load_half(uint32_t dst, int tile, int h, int t128) {
    const __half* src = g_fh + ((size_t)tile * NT + h * 32) * CDIM;
#pragma unroll
    for (int q = 0; q < 8; q++) {
        int i   = t128 + q * 128;
        int row = i >> 5;            // 0..31
        int u   = i & 31;
        cp16(dst + row * ROWB + ((u << 4) ^ ((row & 7) << 4)),
             src + (size_t)row * CDIM + u * 8);
    }
}

// ---------------------------------------------------------------------------
// Kernel 2: R13 structure (3 decoupled key-groups x 4 warps, S m-split,
// O n-split via P smem exchange, 3-slot half-tile ring) + CLOCK STAGGER:
// group g delays its mainloop by g*STAGGER_CYC so the three groups' S/exp/O
// phases interleave instead of colliding on the crossbar / idling the
// tensor pipe during exp.
// ---------------------------------------------------------------------------
__global__ void __launch_bounds__(NTHREADS, 1) attn_kernel(float* __restrict__ out) {
    extern __shared__ char smem[];
    const uint32_t sb = smem_u32(smem);
    const int tid  = threadIdx.x;
    const int lane = tid & 31;
    const int wid  = tid >> 5;
    const int wm   = wid & 3;      // warp-in-group
    const int gg   = wid >> 2;     // key group 0/1/2
    const int t128 = tid & 127;
    const int g    = lane >> 2;
    const int tg   = lane & 3;
    const int qbase = blockIdx.x * MT;

    const int GBASE = (gg == 0) ? 0 : (gg == 1 ? 43 : 86);
    const int NITER = (gg == 2) ? 42 : 43;
    const uint32_t kbase = sb + SK_OFF + (uint32_t)gg * GSTRIDE;
    const uint32_t pbase = sb + SP_OFF + (uint32_t)gg * 8192u;
    char* const pbytes   = smem + SP_OFF + gg * 8192;

    // prologue: Q (all threads) + T0 halves (commit 0) + T1 half0 (commit 1)
    for (int i = tid; i < 2048; i += NTHREADS) {
        int row = i >> 5, u = i & 31;
        cp16(sb + SQ_OFF + row * ROWB + ((u << 4) ^ ((row & 7) << 4)),
             g_fh + (size_t)(qbase + row) * CDIM + u * 8);
    }
    load_half(kbase,              GBASE,     0, t128);
    load_half(kbase + HALF_B,     GBASE,     1, t128);
    CP_COMMIT();
    load_half(kbase + 2 * HALF_B, GBASE + 1, 0, t128);
    CP_COMMIT();
    asm volatile("cp.async.wait_group 1;" ::: "memory");
    __syncthreads();     // Q + all groups' tile0 visible

    // ---- structural phase stagger: group g starts ~g/3 of a tile late ----
    if (gg > 0) {
        unsigned long long t0 = clock64();
        const unsigned long long dly = STAGGER_CYC * (unsigned long long)gg;
        while (clock64() - t0 < dly) { }
    }

    // ldmatrix address components
    const int rowA = wm * 16 + (lane & 15);                 // S-phase A (Q rows)
    const uint32_t aBase = sb + SQ_OFF + rowA * ROWB;
    const int chA = (lane >> 4) << 4, swzA = (rowA & 7) << 4;

    const int rowB0 = (lane & 7) + ((lane >> 4) << 3);      // S-phase B (keys)
    const int chB = ((lane >> 3) & 1) << 4, swzB = (lane & 7) << 4;

    const int rowV0 = (lane & 7) + (((lane >> 3) & 1) << 3); // O-phase B (V, trans)
    const int chV = (lane >> 4) << 4, swzV = (lane & 7) << 4;

    const int rowPA = lane & 15;                             // O-phase A (P tile)
    const uint32_t pldBase = pbase + rowPA * 128;
    const int chP = (lane >> 4) << 4, swzP = (rowPA & 7) << 4;

    uint32_t O[4][8][2];
#pragma unroll
    for (int mb = 0; mb < 4; mb++)
#pragma unroll
        for (int nb = 0; nb < 8; nb++) { O[mb][nb][0] = 0u; O[mb][nb][1] = 0u; }
    float d0 = 0.f, d1 = 0.f;

    int s0 = 0, s1 = 1;   // ring slots of tile(it)'s halves; s2 = 3-s0-s1

#pragma unroll 1
    for (int it = 0; it < NITER; it++) {
        if (it > 0) {
            if (it == NITER - 1) asm volatile("cp.async.wait_group 0;" ::: "memory");
            else                 asm volatile("cp.async.wait_group 1;" ::: "memory");
            asm volatile("bar.sync %0, 128;" :: "r"(gg + 1) : "memory");  // K(it) visible
        }
        const uint32_t h0b = kbase + (uint32_t)s0 * HALF_B;
        const uint32_t h1b = kbase + (uint32_t)s1 * HALF_B;

        // ---- S = Q @ K^T (16 rows x 64 keys per warp, f16 accum) ----
        uint32_t S[8][2];
#pragma unroll
        for (int j = 0; j < 8; j++) { S[j][0] = 0u; S[j][1] = 0u; }
#pragma unroll
        for (int ks = 0; ks < 16; ks++) {
            uint32_t a0, a1, a2, a3;
            ldsm4(aBase + (uint32_t)((chA + 32 * ks) ^ swzA), a0, a1, a2, a3);
#pragma unroll
            for (int j = 0; j < 4; j++) {
                const uint32_t hb = (j < 2) ? h0b : h1b;
                uint32_t b0, b1, b2, b3;
                ldsm4(hb + (rowB0 + 16 * (j & 1)) * ROWB
                         + (uint32_t)((chB + 32 * ks) ^ swzB), b0, b1, b2, b3);
                mmaH(S[2 * j],     a0, a1, a2, a3, b0, b1);
                mmaH(S[2 * j + 1], a0, a1, a2, a3, b2, b3);
            }
        }

        // ---- P = exp(S); denominators; store P slice to group smem tile ----
        {
            __half2 sl = __float2half2_rn(0.f), sh = __float2half2_rn(0.f);
            char* prow = pbytes + (wm * 16 + g) * 128 + 4 * tg;
#pragma unroll
            for (int kb = 0; kb < 4; kb++) {
                uint32_t p0 = exp_h2(S[2 * kb][0]);
                uint32_t p1 = exp_h2(S[2 * kb][1]);
                uint32_t p2 = exp_h2(S[2 * kb + 1][0]);
                uint32_t p3 = exp_h2(S[2 * kb + 1][1]);
                sl = __hadd2(sl, __hadd2(*(__half2*)&p0, *(__half2*)&p2));
                sh = __hadd2(sh, __hadd2(*(__half2*)&p1, *(__half2*)&p3));
                const int u0 = ((2 * kb) ^ g) << 4;
                const int u1 = ((2 * kb + 1) ^ g) << 4;
                *(uint32_t*)(prow + u0)        = p0;
                *(uint32_t*)(prow + 1024 + u0) = p1;
                *(uint32_t*)(prow + u1)        = p2;
                *(uint32_t*)(prow + 1024 + u1) = p3;
            }
            float2 a = __half22float2(sl); d0 += a.x + a.y;
            float2 b = __half22float2(sh); d1 += b.x + b.y;
        }
        asm volatile("bar.sync %0, 128;" :: "r"(gg + 1) : "memory");  // P visible

        // ---- O += P @ V, first half (keys 0-31; V rows in slot s0) ----
#pragma unroll
        for (int ks = 0; ks < 2; ks++) {
            uint32_t pa[4][4];
#pragma unroll
            for (int mb = 0; mb < 4; mb++)
                ldsm4(pldBase + mb * 2048 + (uint32_t)((32 * ks + chP) ^ swzP),
                      pa[mb][0], pa[mb][1], pa[mb][2], pa[mb][3]);
            const uint32_t vrow = h0b + (rowV0 + 16 * ks) * ROWB;
#pragma unroll
            for (int nq = 0; nq < 4; nq++) {
                uint32_t b0, b1, b2, b3;
                ldsm4t(vrow + (uint32_t)((128 * wm + 32 * nq + chV) ^ swzV),
                       b0, b1, b2, b3);
#pragma unroll
                for (int mb = 0; mb < 4; mb++) {
                    mmaH(O[mb][2 * nq],     pa[mb][0], pa[mb][1], pa[mb][2], pa[mb][3], b0, b1);
                    mmaH(O[mb][2 * nq + 1], pa[mb][0], pa[mb][1], pa[mb][2], pa[mb][3], b2, b3);
                }
            }
        }
        // slot s0 (H0(it)) now dead for all 4 warps -> prefetch H1(it+1) into it
        asm volatile("bar.sync %0, 128;" :: "r"(gg + 1) : "memory");
        if (it + 1 < NITER) {
            load_half(kbase + (uint32_t)s0 * HALF_B, GBASE + it + 1, 1, t128);
            CP_COMMIT();
        }

        // ---- O += P @ V, second half (keys 32-63; V rows in slot s1) ----
#pragma unroll
        for (int ks = 2; ks < 4; ks++) {
            uint32_t pa[4][4];
#pragma unroll
            for (int mb = 0; mb < 4; mb++)
                ldsm4(pldBase + mb * 2048 + (uint32_t)((32 * ks + chP) ^ swzP),
                      pa[mb][0], pa[mb][1], pa[mb][2], pa[mb][3]);
            const uint32_t vrow = h1b + (rowV0 + 16 * (ks & 1)) * ROWB;
#pragma unroll
            for (int nq = 0; nq < 4; nq++) {
                uint32_t b0, b1, b2, b3;
                ldsm4t(vrow + (uint32_t)((128 * wm + 32 * nq + chV) ^ swzV),
                       b0, b1, b2, b3);
#pragma unroll
                for (int mb = 0; mb < 4; mb++) {
                    mmaH(O[mb][2 * nq],     pa[mb][0], pa[mb][1], pa[mb][2], pa[mb][3], b0, b1);
                    mmaH(O[mb][2 * nq + 1], pa[mb][0], pa[mb][1], pa[mb][2], pa[mb][3], b2, b3);
                }
            }
        }
        // slot s1 (H1(it)) + P dead -> prefetch H0(it+2) into s1
        asm volatile("bar.sync %0, 128;" :: "r"(gg + 1) : "memory");
        if (it + 2 < NITER) {
            load_half(kbase + (uint32_t)s1 * HALF_B, GBASE + it + 2, 0, t128);
            CP_COMMIT();
        }

        const int s2 = 3 - s0 - s1;   // slot holding H0(it+1)
        s1 = s0; s0 = s2;             // advance ring
    }

    // ---- denominators: quad reduce ----
#pragma unroll
    for (int off = 1; off <= 2; off <<= 1) {
        d0 += __shfl_xor_sync(0xffffffffu, d0, off);
        d1 += __shfl_xor_sync(0xffffffffu, d1, off);
    }

    // ---- epilogue: sum the 3 group O partials into a 64x256 f32 smem tile ----
    __syncthreads();                       // all mainloops done; Q/K/P dead
    float* sDN = (float*)(smem + OFF_DN);
    if (tg == 0) {
        sDN[gg * 64 + wm * 16 + g]     = d0;
        sDN[gg * 64 + wm * 16 + g + 8] = d1;
    }
    if (gg == 0) {
#pragma unroll
        for (int mb = 0; mb < 4; mb++)
#pragma unroll
            for (int nb = 0; nb < 8; nb++) {
                int row = 16 * mb + g;
                int cb  = wm * 256 + nb * 32 + tg * 8;
                *(float2*)(smem + oacc_addr(row, cb))     = __half22float2(*(__half2*)&O[mb][nb][0]);
                *(float2*)(smem + oacc_addr(row + 8, cb)) = __half22float2(*(__half2*)&O[mb][nb][1]);
            }
    }
    __syncthreads();
#pragma unroll 1
    for (int turn = 1; turn <= 2; turn++) {
        if (gg == turn) {
#pragma unroll
            for (int mb = 0; mb < 4; mb++)
#pragma unroll
                for (int nb = 0; nb < 8; nb++) {
                    int row = 16 * mb + g;
                    int cb  = wm * 256 + nb * 32 + tg * 8;
                    float2* a0 = (float2*)(smem + oacc_addr(row, cb));
                    float2* a1 = (float2*)(smem + oacc_addr(row + 8, cb));
                    float2 v0 = __half22float2(*(__half2*)&O[mb][nb][0]);
                    float2 v1 = __half22float2(*(__half2*)&O[mb][nb][1]);
                    float2 c0 = *a0, c1 = *a1;
                    a0->x = c0.x + v0.x; a0->y = c0.y + v0.y;
                    a1->x = c1.x + v1.x; a1->y = c1.y + v1.y;
                }
        }
        __syncthreads();
    }

    // ---- final: blend with f, renormalize rows, write out ----
#pragma unroll 1
    for (int r = wid; r < MT; r += 12) {
        float dsum = sDN[r] + sDN[64 + r] + sDN[128 + r];
        float invd = 0.2f / dsum;
        const float* frow = g_f32 + (size_t)(qbase + r) * CDIM;
        float y[8]; float ss = 0.f;
#pragma unroll
        for (int i = 0; i < 8; i++) {
            int col = lane + 32 * i;
            float o = *(float*)(smem + oacc_addr(r, col * 4));
            y[i] = fmaf(0.8f, frow[col], invd * o);
            ss = fmaf(y[i], y[i], ss);
        }
#pragma unroll
        for (int off = 16; off > 0; off >>= 1) ss += __shfl_xor_sync(0xffffffffu, ss, off);
        float inv = 1.0f / fmaxf(sqrtf(ss), 1e-12f);
        float* orow = out + (size_t)(qbase + r) * CDIM;
#pragma unroll
        for (int i = 0; i < 8; i++) orow[lane + 32 * i] = y[i] * inv;
    }
}

// ---------------------------------------------------------------------------
extern "C" void kernel_launch(void* const* d_in, const int* in_sizes, int n_in,
                              void* d_out, int out_size) {
    const float* feats = (const float*)d_in[0];
    float*       out   = (float*)d_out;
    (void)in_sizes; (void)n_in; (void)out_size;

    cudaFuncSetAttribute(attn_kernel,
                         cudaFuncAttributeMaxDynamicSharedMemorySize, SMEM_TOTAL);

    norm_kernel<<<BN / 8, 256>>>(feats);
    attn_kernel<<<BN / MT, NTHREADS, SMEM_TOTAL>>>(out);
}

// round 17
// speedup vs baseline: 1.3124x; 1.0664x over previous
#include <cuda_runtime.h>
#include <cuda_fp16.h>
#include <cstdint>

#define BN 8192
#define CDIM 256
#define MT 64
#define NT 64
#define NTHREADS 384
#define ROWB 512            // smem bytes per K/Q tile row (256 f16)
#define HALF_B 16384        // one 32-key half-tile

#define SQ_OFF 0                      // Q: 64 x 512B = 32KB
#define SK_OFF 32768                  // K: 3 groups x (3 half-slots x 16KB)
#define GSTRIDE 49152
#define SP_OFF 180224                 // P: 3 groups x 8KB (64 x 128B)
#define SMEM_TOTAL 204800
#define OFF_DN 65536                  // epilogue denom overlay (6 x 64 f32)

#define STAGGER_CYC 2900ull

__device__ float  g_f32[BN * CDIM];   // normalized f (fp32, blend)
__device__ __half g_fh[BN * CDIM];    // normalized f (f16, MMA operand)

// ---------------------------------------------------------------- helpers
__device__ __forceinline__ uint32_t smem_u32(const void* p) {
    uint32_t a;
    asm("{ .reg .u64 t; cvta.to.shared.u64 t, %1; cvt.u32.u64 %0, t; }" : "=r"(a) : "l"(p));
    return a;
}
__device__ __forceinline__ void cp16(uint32_t dst, const void* src) {
    asm volatile("cp.async.cg.shared.global [%0], [%1], 16;" :: "r"(dst), "l"(src));
}
#define CP_COMMIT() asm volatile("cp.async.commit_group;" ::: "memory")

__device__ __forceinline__ void ldsm4(uint32_t a, uint32_t& r0, uint32_t& r1,
                                      uint32_t& r2, uint32_t& r3) {
    asm volatile("ldmatrix.sync.aligned.m8n8.x4.shared.b16 {%0,%1,%2,%3}, [%4];"
                 : "=r"(r0), "=r"(r1), "=r"(r2), "=r"(r3) : "r"(a));
}
__device__ __forceinline__ void ldsm4t(uint32_t a, uint32_t& r0, uint32_t& r1,
                                       uint32_t& r2, uint32_t& r3) {
    asm volatile("ldmatrix.sync.aligned.m8n8.x4.trans.shared.b16 {%0,%1,%2,%3}, [%4];"
                 : "=r"(r0), "=r"(r1), "=r"(r2), "=r"(r3) : "r"(a));
}
__device__ __forceinline__ void mmaH(uint32_t (&c)[2], uint32_t a0, uint32_t a1,
                                     uint32_t a2, uint32_t a3,
                                     uint32_t b0, uint32_t b1) {
    asm volatile("mma.sync.aligned.m16n8k16.row.col.f16.f16.f16.f16 "
                 "{%0,%1}, {%2,%3,%4,%5}, {%6,%7}, {%0,%1};"
                 : "+r"(c[0]), "+r"(c[1])
                 : "r"(a0), "r"(a1), "r"(a2), "r"(a3), "r"(b0), "r"(b1));
}
__device__ __forceinline__ uint32_t exp_h2(uint32_t s) {   // ex2(s*log2e), f16x2
    uint32_t p;
    asm("{ .reg .b32 t;\n\t"
        "mul.rn.f16x2 t, %1, %2;\n\t"
        "ex2.approx.f16x2 %0, t; }"
        : "=r"(p) : "r"(s), "r"(0x3DC53DC5u));
    return p;
}
__device__ __forceinline__ int oacc_addr(int row, int cb) {  // 64x256 f32, 1024B rows
    return row * 1024 + ((((cb >> 4) ^ (row & 7)) << 4) | (cb & 15));
}

// ---------------------------------------------------------------------------
// Kernel 1: row L2-normalize
// ---------------------------------------------------------------------------
__global__ void __launch_bounds__(256) norm_kernel(const float* __restrict__ in) {
    int row  = blockIdx.x * 8 + (threadIdx.x >> 5);
    int lane = threadIdx.x & 31;
    const float* r = in + (size_t)row * CDIM;
    float v[8]; float ss = 0.f;
#pragma unroll
    for (int i = 0; i < 8; i++) { v[i] = r[lane + 32 * i]; ss = fmaf(v[i], v[i], ss); }
#pragma unroll
    for (int o = 16; o > 0; o >>= 1) ss += __shfl_xor_sync(0xffffffffu, ss, o);
    float inv = 1.0f / fmaxf(sqrtf(ss), 1e-12f);
    float*  o32 = g_f32 + (size_t)row * CDIM;
    __half* ofh = g_fh  + (size_t)row * CDIM;
#pragma unroll
    for (int i = 0; i < 8; i++) {
        float x = v[i] * inv;
        o32[lane + 32 * i] = x;
        ofh[lane + 32 * i] = __float2half(x);
    }
}

// Load one 32-key half-tile (16KB) with the group's 128 threads.
__device__ __forceinline__ void load_half(uint32_t dst, int tile, int h, int t128) {
    const __half* src = g_fh + ((size_t)tile * NT + h * 32) * CDIM;
#pragma unroll
    for (int q = 0; q < 8; q++) {
        int i   = t128 + q * 128;
        int row = i >> 5;
        int u   = i & 31;
        cp16(dst + row * ROWB + ((u << 4) ^ ((row & 7) << 4)),
             src + (size_t)row * CDIM + u * 8);
    }
}

// ---------------------------------------------------------------------------
// Kernel 2: R13/R15 structure + QUADRANT-SPLIT S GEMM: warp (qr,qc) computes
// the 32-row x 32-key quadrant of S -> K fragments read 2x instead of 4x per
// group (S-phase LDS 40->32 KB/warp). O phase (n-split via P exchange),
// half-tile ring and group stagger unchanged.
// ---------------------------------------------------------------------------
__global__ void __launch_bounds__(NTHREADS, 1) attn_kernel(float* __restrict__ out) {
    extern __shared__ char smem[];
    const uint32_t sb = smem_u32(smem);
    const int tid  = threadIdx.x;
    const int lane = tid & 31;
    const int wid  = tid >> 5;
    const int wm   = wid & 3;      // warp-in-group
    const int gg   = wid >> 2;     // key group 0/1/2
    const int t128 = tid & 127;
    const int g    = lane >> 2;
    const int tg   = lane & 3;
    const int qr   = wm >> 1;      // quadrant row block (32 q-rows)
    const int qc   = wm & 1;       // quadrant key block (32 keys)
    const int qbase = blockIdx.x * MT;

    const int GBASE = (gg == 0) ? 0 : (gg == 1 ? 43 : 86);
    const int NITER = (gg == 2) ? 42 : 43;
    const uint32_t kbase = sb + SK_OFF + (uint32_t)gg * GSTRIDE;
    const uint32_t pbase = sb + SP_OFF + (uint32_t)gg * 8192u;
    char* const pbytes   = smem + SP_OFF + gg * 8192;

    // prologue: Q (all threads) + T0 halves (commit 0) + T1 half0 (commit 1)
    for (int i = tid; i < 2048; i += NTHREADS) {
        int row = i >> 5, u = i & 31;
        cp16(sb + SQ_OFF + row * ROWB + ((u << 4) ^ ((row & 7) << 4)),
             g_fh + (size_t)(qbase + row) * CDIM + u * 8);
    }
    load_half(kbase,              GBASE,     0, t128);
    load_half(kbase + HALF_B,     GBASE,     1, t128);
    CP_COMMIT();
    load_half(kbase + 2 * HALF_B, GBASE + 1, 0, t128);
    CP_COMMIT();
    asm volatile("cp.async.wait_group 1;" ::: "memory");
    __syncthreads();

    // structural phase stagger (kept from R15; neutral-positive)
    if (gg > 0) {
        unsigned long long t0 = clock64();
        const unsigned long long dly = STAGGER_CYC * (unsigned long long)gg;
        while (clock64() - t0 < dly) { }
    }

    // ldmatrix address components
    // S-phase A (Q rows of this quadrant): rows 32*qr + 16*rb + (lane&15)
    const uint32_t aBase = sb + SQ_OFF + (32 * qr + (lane & 15)) * ROWB;
    const int chA = (lane >> 4) << 4, swzA = (lane & 7) << 4;
    // S-phase B (keys, local within this warp's half-tile)
    const int rowB0 = (lane & 7) + ((lane >> 4) << 3);
    const int chB = ((lane >> 3) & 1) << 4, swzB = (lane & 7) << 4;
    // O-phase B (V f16, trans)
    const int rowV0 = (lane & 7) + (((lane >> 3) & 1) << 3);
    const int chV = (lane >> 4) << 4, swzV = (lane & 7) << 4;
    // O-phase A (P tile)
    const int rowPA = lane & 15;
    const uint32_t pldBase = pbase + rowPA * 128;
    const int chP = (lane >> 4) << 4, swzP = (rowPA & 7) << 4;

    uint32_t O[4][8][2];
#pragma unroll
    for (int mb = 0; mb < 4; mb++)
#pragma unroll
        for (int nb = 0; nb < 8; nb++) { O[mb][nb][0] = 0u; O[mb][nb][1] = 0u; }
    float dn[4];                 // rows 32qr+16rb+{g, g+8}, this warp's 32 keys
#pragma unroll
    for (int i = 0; i < 4; i++) dn[i] = 0.f;

    int s0 = 0, s1 = 1;          // ring slots of tile(it)'s halves

#pragma unroll 1
    for (int it = 0; it < NITER; it++) {
        if (it > 0) {
            if (it == NITER - 1) asm volatile("cp.async.wait_group 0;" ::: "memory");
            else                 asm volatile("cp.async.wait_group 1;" ::: "memory");
            asm volatile("bar.sync %0, 128;" :: "r"(gg + 1) : "memory");
        }
        const uint32_t h0b = kbase + (uint32_t)s0 * HALF_B;
        const uint32_t h1b = kbase + (uint32_t)s1 * HALF_B;
        const uint32_t hqb = qc ? h1b : h0b;   // this warp's S-phase key half

        // ---- S quadrant: 32 rows x 32 keys, f16 accum ----
        uint32_t S[2][4][2];
#pragma unroll
        for (int rb = 0; rb < 2; rb++)
#pragma unroll
            for (int nb = 0; nb < 4; nb++) { S[rb][nb][0] = 0u; S[rb][nb][1] = 0u; }
#pragma unroll
        for (int ks = 0; ks < 16; ks++) {
            const uint32_t aoff = (uint32_t)((chA + 32 * ks) ^ swzA);
            uint32_t a0, a1, a2, a3, c0, c1, c2, c3;
            ldsm4(aBase + aoff,              a0, a1, a2, a3);   // rows 32qr..+15
            ldsm4(aBase + 16 * ROWB + aoff,  c0, c1, c2, c3);   // rows 32qr+16..+31
#pragma unroll
            for (int jb = 0; jb < 2; jb++) {
                uint32_t b0, b1, b2, b3;
                ldsm4(hqb + (rowB0 + 16 * jb) * ROWB
                          + (uint32_t)((chB + 32 * ks) ^ swzB), b0, b1, b2, b3);
                mmaH(S[0][2 * jb],     a0, a1, a2, a3, b0, b1);
                mmaH(S[0][2 * jb + 1], a0, a1, a2, a3, b2, b3);
                mmaH(S[1][2 * jb],     c0, c1, c2, c3, b0, b1);
                mmaH(S[1][2 * jb + 1], c0, c1, c2, c3, b2, b3);
            }
        }

        // ---- P = exp(S); per-quadrant denominators; store to P tile ----
#pragma unroll
        for (int rb = 0; rb < 2; rb++) {
            __half2 sl = __float2half2_rn(0.f), sh = __float2half2_rn(0.f);
            char* prow = pbytes + (32 * qr + 16 * rb + g) * 128 + 4 * tg;
#pragma unroll
            for (int kb = 0; kb < 4; kb++) {
                uint32_t plo = exp_h2(S[rb][kb][0]);   // row ..+g
                uint32_t phi = exp_h2(S[rb][kb][1]);   // row ..+g+8
                sl = __hadd2(sl, *(__half2*)&plo);
                sh = __hadd2(sh, *(__half2*)&phi);
                const int u = ((4 * qc + kb) ^ g) << 4;
                *(uint32_t*)(prow + u)        = plo;
                *(uint32_t*)(prow + 1024 + u) = phi;
            }
            float2 a = __half22float2(sl); dn[2 * rb]     += a.x + a.y;
            float2 b = __half22float2(sh); dn[2 * rb + 1] += b.x + b.y;
        }
        asm volatile("bar.sync %0, 128;" :: "r"(gg + 1) : "memory");  // P visible

        // ---- O += P @ V, first half (keys 0-31; slot s0) ----
#pragma unroll
        for (int ks = 0; ks < 2; ks++) {
            uint32_t pa[4][4];
#pragma unroll
            for (int mb = 0; mb < 4; mb++)
                ldsm4(pldBase + mb * 2048 + (uint32_t)((32 * ks + chP) ^ swzP),
                      pa[mb][0], pa[mb][1], pa[mb][2], pa[mb][3]);
            const uint32_t vrow = h0b + (rowV0 + 16 * ks) * ROWB;
#pragma unroll
            for (int nq = 0; nq < 4; nq++) {
                uint32_t b0, b1, b2, b3;
                ldsm4t(vrow + (uint32_t)((128 * wm + 32 * nq + chV) ^ swzV),
                       b0, b1, b2, b3);
#pragma unroll
                for (int mb = 0; mb < 4; mb++) {
                    mmaH(O[mb][2 * nq],     pa[mb][0], pa[mb][1], pa[mb][2], pa[mb][3], b0, b1);
                    mmaH(O[mb][2 * nq + 1], pa[mb][0], pa[mb][1], pa[mb][2], pa[mb][3], b2, b3);
                }
            }
        }
        asm volatile("bar.sync %0, 128;" :: "r"(gg + 1) : "memory");
        if (it + 1 < NITER) {
            load_half(kbase + (uint32_t)s0 * HALF_B, GBASE + it + 1, 1, t128);
            CP_COMMIT();
        }

        // ---- O += P @ V, second half (keys 32-63; slot s1) ----
#pragma unroll
        for (int ks = 2; ks < 4; ks++) {
            uint32_t pa[4][4];
#pragma unroll
            for (int mb = 0; mb < 4; mb++)
                ldsm4(pldBase + mb * 2048 + (uint32_t)((32 * ks + chP) ^ swzP),
                      pa[mb][0], pa[mb][1], pa[mb][2], pa[mb][3]);
            const uint32_t vrow = h1b + (rowV0 + 16 * (ks & 1)) * ROWB;
#pragma unroll
            for (int nq = 0; nq < 4; nq++) {
                uint32_t b0, b1, b2, b3;
                ldsm4t(vrow + (uint32_t)((128 * wm + 32 * nq + chV) ^ swzV),
                       b0, b1, b2, b3);
#pragma unroll
                for (int mb = 0; mb < 4; mb++) {
                    mmaH(O[mb][2 * nq],     pa[mb][0], pa[mb][1], pa[mb][2], pa[mb][3], b0, b1);
                    mmaH(O[mb][2 * nq + 1], pa[mb][0], pa[mb][1], pa[mb][2], pa[mb][3], b2, b3);
                }
            }
        }
        asm volatile("bar.sync %0, 128;" :: "r"(gg + 1) : "memory");
        if (it + 2 < NITER) {
            load_half(kbase + (uint32_t)s1 * HALF_B, GBASE + it + 2, 0, t128);
            CP_COMMIT();
        }

        const int s2 = 3 - s0 - s1;
        s1 = s0; s0 = s2;
    }

    // ---- denominators: quad reduce over tg; publish 6 partial tables ----
#pragma unroll
    for (int i = 0; i < 4; i++)
#pragma unroll
        for (int off = 1; off <= 2; off <<= 1)
            dn[i] += __shfl_xor_sync(0xffffffffu, dn[i], off);

    float* sDN = (float*)(smem + OFF_DN);   // [gg*2+qc][64 rows]
    __syncthreads();                         // all mainloops done; K region dead
    if (tg == 0) {
        const int base = (gg * 2 + qc) * 64 + 32 * qr;
        sDN[base + g]          = dn[0];
        sDN[base + g + 8]      = dn[1];
        sDN[base + 16 + g]     = dn[2];
        sDN[base + 16 + g + 8] = dn[3];
    }

    // ---- epilogue: sum the 3 group O partials into a 64x256 f32 smem tile ----
    if (gg == 0) {
#pragma unroll
        for (int mb = 0; mb < 4; mb++)
#pragma unroll
            for (int nb = 0; nb < 8; nb++) {
                int row = 16 * mb + g;
                int cb  = wm * 256 + nb * 32 + tg * 8;
                *(float2*)(smem + oacc_addr(row, cb))     = __half22float2(*(__half2*)&O[mb][nb][0]);
                *(float2*)(smem + oacc_addr(row + 8, cb)) = __half22float2(*(__half2*)&O[mb][nb][1]);
            }
    }
    __syncthreads();
#pragma unroll 1
    for (int turn = 1; turn <= 2; turn++) {
        if (gg == turn) {
#pragma unroll
            for (int mb = 0; mb < 4; mb++)
#pragma unroll
                for (int nb = 0; nb < 8; nb++) {
                    int row = 16 * mb + g;
                    int cb  = wm * 256 + nb * 32 + tg * 8;
                    float2* a0 = (float2*)(smem + oacc_addr(row, cb));
                    float2* a1 = (float2*)(smem + oacc_addr(row + 8, cb));
                    float2 v0 = __half22float2(*(__half2*)&O[mb][nb][0]);
                    float2 v1 = __half22float2(*(__half2*)&O[mb][nb][1]);
                    float2 c0 = *a0, c1 = *a1;
                    a0->x = c0.x + v0.x; a0->y = c0.y + v0.y;
                    a1->x = c1.x + v1.x; a1->y = c1.y + v1.y;
                }
        }
        __syncthreads();
    }

    // ---- final: blend with f, renormalize rows, write out ----
#pragma unroll 1
    for (int r = wid; r < MT; r += 12) {
        float dsum = 0.f;
#pragma unroll
        for (int e = 0; e < 6; e++) dsum += sDN[e * 64 + r];
        float invd = 0.2f / dsum;
        const float* frow = g_f32 + (size_t)(qbase + r) * CDIM;
        float y[8]; float ss = 0.f;
#pragma unroll
        for (int i = 0; i < 8; i++) {
            int col = lane + 32 * i;
            float o = *(float*)(smem + oacc_addr(r, col * 4));
            y[i] = fmaf(0.8f, frow[col], invd * o);
            ss = fmaf(y[i], y[i], ss);
        }
#pragma unroll
        for (int off = 16; off > 0; off >>= 1) ss += __shfl_xor_sync(0xffffffffu, ss, off);
        float inv = 1.0f / fmaxf(sqrtf(ss), 1e-12f);
        float* orow = out + (size_t)(qbase + r) * CDIM;
#pragma unroll
        for (int i = 0; i < 8; i++) orow[lane + 32 * i] = y[i] * inv;
    }
}

// ---------------------------------------------------------------------------
extern "C" void kernel_launch(void* const* d_in, const int* in_sizes, int n_in,
                              void* d_out, int out_size) {
    const float* feats = (const float*)d_in[0];
    float*       out   = (float*)d_out;
    (void)in_sizes; (void)n_in; (void)out_size;

    cudaFuncSetAttribute(attn_kernel,
                         cudaFuncAttributeMaxDynamicSharedMemorySize, SMEM_TOTAL);

    norm_kernel<<<BN / 8, 256>>>(feats);
    attn_kernel<<<BN / MT, NTHREADS, SMEM_TOTAL>>>(out);
}